// round 6
// baseline (speedup 1.0000x reference)
#include <cuda_runtime.h>
#include <math.h>

#define DI    104          // input feature dim
#define DO    144          // conv output dim (incl. gates)
#define SO    120          // final output channels
#define NB    16           // radial basis count
#define NPTS  1024
#define MPTS  1024
#define BATCH 4
#define TN    8            // n-points per CTA
#define CM    32           // m-chunk
#define THREADS 256

typedef unsigned long long ull;

// Transposed W: Wt[k][i][o] (o contiguous)
__device__ float g_Wt[NB * DI * DO];
// chain constants C_k = exp((64/225)*(2k-1)), k=1..15
__device__ float g_cs[16];

__device__ __forceinline__ ull pack2(float x, float y) {
    ull r; asm("mov.b64 %0, {%1, %2};" : "=l"(r) : "f"(x), "f"(y)); return r;
}
__device__ __forceinline__ void unpack2(ull v, float& x, float& y) {
    asm("mov.b64 {%0, %1}, %2;" : "=f"(x), "=f"(y) : "l"(v));
}
__device__ __forceinline__ ull fma2(ull a, ull b, ull c) {
    ull d; asm("fma.rn.f32x2 %0, %1, %2, %3;" : "=l"(d) : "l"(a), "l"(b), "l"(c));
    return d;
}

union F4U { float4 f; ull u[2]; };

__global__ void initConsts() {
    int k = threadIdx.x;
    if (k < 16) g_cs[k] = (float)exp((64.0 / 225.0) * (2.0 * k - 1.0));
}

__global__ void transposeW(const float* __restrict__ W) {
    int idx = blockIdx.x * blockDim.x + threadIdx.x;
    if (idx < NB * DI * DO) {
        int k = idx / (DI * DO);
        int r = idx % (DI * DO);
        int i = r / DO;
        int o = r % DO;
        g_Wt[idx] = W[(k * DO + o) * DI + i];
    }
}

// smem layout (floats):
//  phase 1: feat_s [104][33] = 3432 | phi_s [32m][8n][16k] = 4096  (union base)
//  phase 2: tmp  [16k][104i][8n] = 13312 | y_s [144][8] = 1152  -> 14464
//  cs_s at 14464 (alive phase 1 only; y_s ends exactly at 14464)
#define SMEM_FLOATS 14480

__global__ __launch_bounds__(THREADS, 2) void se3conv(
    const float* __restrict__ feat,   // [B, DI, M]
    const float* __restrict__ diff,   // [B, N, M, 3]
    const float* __restrict__ mask,   // [B, N, M]
    float* __restrict__ out)          // [B, SO, N]
{
    extern __shared__ __align__(16) float smem[];
    float*  feat_s = smem;                  // pitch 33
    float*  phi_s  = smem + DI * 33;        // [m][n8][16]
    float*  cs_s   = smem + 14464;
    float4* tmp4   = (float4*)smem;         // [(k*DI+i)*2 + g]
    float*  y_s    = smem + NB * DI * TN;   // [o][8]

    const int tid  = threadIdx.x;
    const int b    = blockIdx.x >> 7;            // 128 n-tiles per batch
    const int n0   = (blockIdx.x & 127) * TN;
    const int gi   = tid >> 7;                   // i-group (n-half)
    const int li   = tid & 127;                  // i lane

    if (tid < 16) cs_s[tid] = g_cs[tid];

    ull acc[4][8];
#pragma unroll
    for (int n = 0; n < 4; n++)
#pragma unroll
        for (int q = 0; q < 8; q++) acc[n][q] = 0ull;

    const int pn = tid >> 5;   // 0..7 : n for phi production
    const int pm = tid & 31;   // m within chunk
    const float* diff_p = diff + ((size_t)(b * NPTS + n0 + pn)) * MPTS * 3;
    const float* mask_p = mask + ((size_t)(b * NPTS + n0 + pn)) * MPTS;
    const float* feat_p = feat + (size_t)b * DI * MPTS;

    __syncthreads();   // cs_s visible

    for (int mc = 0; mc < MPTS; mc += CM) {
        // --- stage features [104][32], coalesced, pitch 33 ---
#pragma unroll
        for (int idx = tid; idx < DI * CM; idx += THREADS) {
            int ii = idx >> 5, mm = idx & 31;
            feat_s[ii * 33 + mm] = feat_p[ii * MPTS + mc + mm];
        }

        // --- phi for this thread's (n,m): 2 EX2 + chain instead of 16 EX2 ---
        {
            int gm = mc + pm;
            float dx = diff_p[gm * 3 + 0];
            float dy = diff_p[gm * 3 + 1];
            float dz = diff_p[gm * 3 + 2];
            float msk = mask_p[gm];
            float r2 = fmaf(dx, dx, fmaf(dy, dy, fmaf(dz, dz, 1e-12f)));
            float r  = r2 * rsqrtf(r2);
            float d15 = r - 2.0f;
            float p = __expf(-16.0f * d15 * d15) * msk;    // phi_15 * mask
            float w = __expf(-4.2666667f * r);             // exp(-32*delta*r)
            float ph[16];
            ph[15] = p;
#pragma unroll
            for (int k = 15; k >= 1; k--) {
                p = p * (w * cs_s[k]);
                ph[k - 1] = p;
            }
            float4* dst = (float4*)(phi_s + (pm * TN + pn) * 16);
#pragma unroll
            for (int q = 0; q < 4; q++)
                dst[q] = make_float4(ph[4 * q], ph[4 * q + 1], ph[4 * q + 2], ph[4 * q + 3]);
        }
        __syncthreads();

        // --- tmp[n][k] += phi[n][m][k] * feat[i][m] (FFMA2) ---
        if (li < DI) {
#pragma unroll 2
            for (int m = 0; m < CM; m++) {
                float f = feat_s[li * 33 + m];
                ull ff = pack2(f, f);
                const float4* pp = (const float4*)phi_s + (m * TN + gi * 4) * 4;
#pragma unroll
                for (int n = 0; n < 4; n++) {
#pragma unroll
                    for (int q = 0; q < 4; q++) {
                        F4U p; p.f = pp[n * 4 + q];
                        acc[n][2 * q]     = fma2(p.u[0], ff, acc[n][2 * q]);
                        acc[n][2 * q + 1] = fma2(p.u[1], ff, acc[n][2 * q + 1]);
                    }
                }
            }
        }
        __syncthreads();   // chunk consumed before restaging
    }

    // --- spill tmp to smem: [k][i] -> 2x float4 over 8 n ---
    if (li < DI) {
#pragma unroll
        for (int q = 0; q < 8; q++) {
            float a0, a1, b0, b1, c0, c1, d0, d1;
            unpack2(acc[0][q], a0, a1);
            unpack2(acc[1][q], b0, b1);
            unpack2(acc[2][q], c0, c1);
            unpack2(acc[3][q], d0, d1);
            tmp4[((2 * q)     * DI + li) * 2 + gi] = make_float4(a0, b0, c0, d0);
            tmp4[((2 * q + 1) * DI + li) * 2 + gi] = make_float4(a1, b1, c1, d1);
        }
    }
    __syncthreads();

    // --- stage B: y[o][n] = sum_{k,i} tmp[k][i][n] * Wt[k][i][o] ---
    if (tid < DO) {
        const int o = tid;
        ull y0 = 0ull, y1 = 0ull, y2 = 0ull, y3 = 0ull;
        for (int k = 0; k < NB; k++) {
            const float*  wrow = g_Wt + k * DI * DO;
            const float4* trow = tmp4 + k * DI * 2;
#pragma unroll 4
            for (int i2 = 0; i2 < DI; i2++) {
                F4U t0, t1;
                t0.f = trow[i2 * 2 + 0];
                t1.f = trow[i2 * 2 + 1];
                float wv = wrow[i2 * DO + o];
                ull ww = pack2(wv, wv);
                y0 = fma2(t0.u[0], ww, y0);
                y1 = fma2(t0.u[1], ww, y1);
                y2 = fma2(t1.u[0], ww, y2);
                y3 = fma2(t1.u[1], ww, y3);
            }
        }
        float a, b2, c, d;
        float4* yd = (float4*)(y_s + o * TN);
        unpack2(y0, a, b2); unpack2(y1, c, d);
        yd[0] = make_float4(a, b2, c, d);
        unpack2(y2, a, b2); unpack2(y3, c, d);
        yd[1] = make_float4(a, b2, c, d);
    }
    __syncthreads();

    // --- gating epilogue ---
    for (int idx = tid; idx < SO * TN; idx += THREADS) {
        int c = idx >> 3;
        int n = idx & 7;
        float v = y_s[c * TN + n];
        float res;
        if (c < 32) {
            res = fmaxf(v, 0.0f);
        } else if (c < 80) {
            int j = (c - 32) / 3;
            float g = y_s[(120 + j) * TN + n];
            res = v * __fdividef(1.0f, 1.0f + __expf(-g));
        } else {
            int j = (c - 80) / 5;
            float g = y_s[(136 + j) * TN + n];
            res = v * __fdividef(1.0f, 1.0f + __expf(-g));
        }
        out[((size_t)b * SO + c) * NPTS + n0 + n] = res;
    }
}

extern "C" void kernel_launch(void* const* d_in, const int* in_sizes, int n_in,
                              void* d_out, int out_size) {
    (void)in_sizes; (void)n_in; (void)out_size;
    const float* feat = (const float*)d_in[0];
    const float* diff = (const float*)d_in[1];
    const float* mask = (const float*)d_in[2];
    const float* W    = (const float*)d_in[3];

    cudaFuncSetAttribute(se3conv, cudaFuncAttributeMaxDynamicSharedMemorySize,
                         SMEM_FLOATS * sizeof(float));

    initConsts<<<1, 16>>>();
    transposeW<<<(NB * DI * DO + 255) / 256, 256>>>(W);
    se3conv<<<BATCH * (NPTS / TN), THREADS, SMEM_FLOATS * sizeof(float)>>>(
        feat, diff, mask, (float*)d_out);
}

// round 12
// speedup vs baseline: 2.8796x; 2.8796x over previous
#include <cuda_runtime.h>
#include <cuda_bf16.h>
#include <cstdint>

#define DI    104
#define DO    144
#define SO    120
#define NB    16
#define NPTS  1024
#define MPTS  1024
#define BATCH 4

typedef unsigned long long ull;
typedef unsigned int u32;

// ---------------- device scratch (no allocation) ----------------
__device__ float         g_tmp[(size_t)BATCH * NPTS * NB * DI];   // [b][n][k][i]
__device__ __nv_bfloat16 g_fh[(size_t)BATCH * 128 * MPTS];        // feat hi, i pad 128
__device__ __nv_bfloat16 g_fl[(size_t)BATCH * 128 * MPTS];        // feat lo

// ---------------- helpers ----------------
__device__ __forceinline__ u32 smem_u32(const void* p) {
    u32 a;
    asm("{ .reg .u64 t; cvta.to.shared.u64 t, %1; cvt.u32.u64 %0, t; }" : "=r"(a) : "l"(p));
    return a;
}
#define SWZ(o) ((o) ^ (((o) >> 3) & 0x70))

__device__ __forceinline__ ull pack2(float x, float y) {
    ull r; asm("mov.b64 %0, {%1, %2};" : "=l"(r) : "f"(x), "f"(y)); return r;
}
__device__ __forceinline__ void unpack2(ull v, float& x, float& y) {
    asm("mov.b64 {%0, %1}, %2;" : "=f"(x), "=f"(y) : "l"(v));
}
__device__ __forceinline__ ull fma2(ull a, ull b, ull c) {
    ull d; asm("fma.rn.f32x2 %0, %1, %2, %3;" : "=l"(d) : "l"(a), "l"(b), "l"(c));
    return d;
}
union F4U { float4 f; ull u[2]; };

__device__ __forceinline__ void ldsm4(u32& r0, u32& r1, u32& r2, u32& r3, u32 a) {
    asm volatile("ldmatrix.sync.aligned.m8n8.x4.shared.b16 {%0,%1,%2,%3}, [%4];"
        : "=r"(r0), "=r"(r1), "=r"(r2), "=r"(r3) : "r"(a));
}
__device__ __forceinline__ void ldsm2(u32& r0, u32& r1, u32 a) {
    asm volatile("ldmatrix.sync.aligned.m8n8.x2.shared.b16 {%0,%1}, [%2];"
        : "=r"(r0), "=r"(r1) : "r"(a));
}
__device__ __forceinline__ void mma16816(float* c, const u32* a, const u32* b) {
    asm volatile("mma.sync.aligned.m16n8k16.row.col.f32.bf16.bf16.f32 "
        "{%0,%1,%2,%3}, {%4,%5,%6,%7}, {%8,%9}, {%0,%1,%2,%3};"
        : "+f"(c[0]), "+f"(c[1]), "+f"(c[2]), "+f"(c[3])
        : "r"(a[0]), "r"(a[1]), "r"(a[2]), "r"(a[3]), "r"(b[0]), "r"(b[1]));
}
__device__ __forceinline__ void sts32(u32 addr, u32 v) {
    asm volatile("st.shared.b32 [%0], %1;" :: "r"(addr), "r"(v));
}
__device__ __forceinline__ void sts128(u32 addr, uint4 v) {
    asm volatile("st.shared.v4.b32 [%0], {%1,%2,%3,%4};"
        :: "r"(addr), "r"(v.x), "r"(v.y), "r"(v.z), "r"(v.w));
}

// ---------------- pre-kernel: split features hi/lo bf16, pad i to 128 ----------------
__global__ void featSplit(const float* __restrict__ feat) {
    int idx = blockIdx.x * 256 + threadIdx.x;   // B*128*1024 total
    int m = idx & 1023;
    int r = (idx >> 10) & 127;
    int b = idx >> 17;
    float f = (r < DI) ? feat[((size_t)b * DI + r) * MPTS + m] : 0.0f;
    __nv_bfloat16 h = __float2bfloat16(f);
    float lo = f - __bfloat162float(h);
    g_fh[idx] = h;
    g_fl[idx] = __float2bfloat16(lo);
}

// ---------------- kernel A: HMMA GEMM  tmp[ch][i] = sum_m phi[ch][m]*feat[i][m] ----------------
// smem: 4 SW128 tiles of [128 rows][64 cols] bf16 (16 KB each)
#define OFF_PH 0
#define OFF_PL 16384
#define OFF_FH 32768
#define OFF_FL 49152
#define SMEMA_BYTES 65536

__global__ __launch_bounds__(256, 2) void se3convA(
    const float* __restrict__ diff,   // [B, N, M, 3]
    const float* __restrict__ mask)   // [B, N, M]
{
    extern __shared__ __align__(1024) char smA[];
    const u32 sb = smem_u32(smA);
    const int tid  = threadIdx.x;
    const int lane = tid & 31;
    const int wid  = tid >> 5;
    const int b  = blockIdx.x >> 7;
    const int n0 = (blockIdx.x & 127) * 8;
    const int wm = wid >> 2;    // ch half   (64 rows)
    const int wn = wid & 3;     // i quarter (32 cols)

    // chain constants: step multiplier from phi_k to phi_{k-1} is w * exp((64/225)(2k-1)).
    // Walking k = 15 -> 1 these DECREASE: seed at exp((64/225)*29), decay by exp(-128/225).
    const float CTOP = __expf(8.2488890f);    // exp((64/225)*29)
    const float CDEC = __expf(-0.5688889f);   // exp(-128/225)

    float c[4][4][4];
#pragma unroll
    for (int mt = 0; mt < 4; mt++)
#pragma unroll
        for (int nb = 0; nb < 4; nb++)
#pragma unroll
            for (int q = 0; q < 4; q++) c[mt][nb][q] = 0.0f;

    // phi producer role: warp w handles n = w, lane = m-pair index
    const int pn  = wid;
    const int pm0 = lane;
    const float* diff_p = diff + ((size_t)(b * NPTS + n0 + pn)) * MPTS * 3;
    const float* mask_p = mask + ((size_t)(b * NPTS + n0 + pn)) * MPTS;
    const uint4* fh_g = (const uint4*)(g_fh + (size_t)b * 128 * MPTS);  // rows of 128 uint4
    const uint4* fl_g = (const uint4*)(g_fl + (size_t)b * 128 * MPTS);

    // ldmatrix per-lane address components (byte offsets within 128B rows)
    const u32 aRow  = (u32)(lane & 15);
    const u32 aColB = (u32)((lane >> 4) * 16);
    const u32 bRow  = (u32)(lane & 7);
    const u32 bColB = (u32)(((lane >> 3) & 1) * 16);

    for (int cc = 0; cc < 16; cc++) {
        __syncthreads();   // previous chunk fully consumed

        // --- stage feat hi/lo [128 i][64 m] bf16, SW128 swizzled ---
        {
            const int col0 = 8 * cc;
#pragma unroll
            for (int t = 0; t < 4; t++) {
                int idx = tid + t * 256;
                int r = idx >> 3, j = idx & 7;
                u32 sw = SWZ((u32)(r * 128 + j * 16));
                sts128(sb + OFF_FH + sw, fh_g[r * 128 + col0 + j]);
                sts128(sb + OFF_FL + sw, fl_g[r * 128 + col0 + j]);
            }
        }

        // --- phi hi/lo [128 ch][64 m] bf16: 2 m per thread, downward chain ---
        {
            const int m = cc * 64 + 2 * pm0;
            const float2* dp = (const float2*)(diff_p + (size_t)3 * m);
            float2 d0 = dp[0], d1 = dp[1], d2 = dp[2];
            float2 mk = *(const float2*)(mask_p + m);
            float r2a = fmaf(d0.x, d0.x, fmaf(d0.y, d0.y, fmaf(d1.x, d1.x, 1e-12f)));
            float r2b = fmaf(d1.y, d1.y, fmaf(d2.x, d2.x, fmaf(d2.y, d2.y, 1e-12f)));
            float ra = r2a * rsqrtf(r2a);
            float rb = r2b * rsqrtf(r2b);
            float ea = ra - 2.0f, eb = rb - 2.0f;
            float pa = __expf(-16.0f * ea * ea) * mk.x;     // phi_15 * mask
            float pb = __expf(-16.0f * eb * eb) * mk.y;
            float wa = __expf(-4.26666667f * ra);           // exp(-32*delta*r)
            float wb = __expf(-4.26666667f * rb);
            float ua = wa * CTOP;                           // w * cs[15]  (largest)
            float ub = wb * CTOP;
            const u32 colb = 4u * (u32)pm0;
#pragma unroll
            for (int k = 15; k >= 0; k--) {
                // store phi_k = (pa, pb)
                u32 hp;
                asm("cvt.rn.satfinite.bf16x2.f32 %0, %1, %2;" : "=r"(hp) : "f"(pb), "f"(pa));
                float ahf = __uint_as_float(hp << 16);
                float bhf = __uint_as_float(hp & 0xFFFF0000u);
                u32 lp;
                asm("cvt.rn.satfinite.bf16x2.f32 %0, %1, %2;"
                    : "=r"(lp) : "f"(pb - bhf), "f"(pa - ahf));
                u32 off = SWZ((u32)((pn * 16 + k) * 128) + colb);
                sts32(sb + OFF_PH + off, hp);
                sts32(sb + OFF_PL + off, lp);
                if (k > 0) { pa *= ua; pb *= ub; ua *= CDEC; ub *= CDEC; }
            }
        }
        __syncthreads();

        // --- MMA: 4 k-steps of 16, 3-way split product into one fp32 acc ---
#pragma unroll
        for (int ks = 0; ks < 4; ks++) {
            const u32 mb = (u32)(ks * 32);   // byte col base
            u32 aph[4][4], apl[4][4], bf[4][2];
#pragma unroll
            for (int mt = 0; mt < 4; mt++) {
                u32 row = (u32)(wm * 64 + mt * 16) + aRow;
                u32 off = SWZ(row * 128 + mb + aColB);
                ldsm4(aph[mt][0], aph[mt][1], aph[mt][2], aph[mt][3], sb + OFF_PH + off);
                ldsm4(apl[mt][0], apl[mt][1], apl[mt][2], apl[mt][3], sb + OFF_PL + off);
            }
#pragma unroll
            for (int nb = 0; nb < 4; nb++) {
                u32 row = (u32)(wn * 32 + nb * 8) + bRow;
                u32 off = SWZ(row * 128 + mb + bColB);
                ldsm2(bf[nb][0], bf[nb][1], sb + OFF_FH + off);
            }
#pragma unroll
            for (int mt = 0; mt < 4; mt++)
#pragma unroll
                for (int nb = 0; nb < 4; nb++) {
                    mma16816(c[mt][nb], aph[mt], bf[nb]);   // ph*fh
                    mma16816(c[mt][nb], apl[mt], bf[nb]);   // pl*fh
                }
#pragma unroll
            for (int nb = 0; nb < 4; nb++) {
                u32 row = (u32)(wn * 32 + nb * 8) + bRow;
                u32 off = SWZ(row * 128 + mb + bColB);
                ldsm2(bf[nb][0], bf[nb][1], sb + OFF_FL + off);
            }
#pragma unroll
            for (int mt = 0; mt < 4; mt++)
#pragma unroll
                for (int nb = 0; nb < 4; nb++)
                    mma16816(c[mt][nb], aph[mt], bf[nb]);   // ph*fl
        }
    }

    // --- store C: rows ch (i contiguous), coalesced float2 ---
    const size_t obase = ((size_t)(b * NPTS + n0)) * NB * DI;
#pragma unroll
    for (int mt = 0; mt < 4; mt++) {
        int ch0 = wm * 64 + mt * 16 + (lane >> 2);
        float* r0 = g_tmp + obase + (size_t)ch0 * DI;
#pragma unroll
        for (int nb = 0; nb < 4; nb++) {
            int i0 = wn * 32 + nb * 8 + (lane & 3) * 2;
            if (i0 < DI) {
                *(float2*)(r0 + i0)          = make_float2(c[mt][nb][0], c[mt][nb][1]);
                *(float2*)(r0 + 8 * DI + i0) = make_float2(c[mt][nb][2], c[mt][nb][3]);
            }
        }
    }
}

// ---------------- kernel B: y = W x tmp (FFMA2) + gating epilogue ----------------
#define TB 288

__global__ __launch_bounds__(TB, 1) void se3convB(
    const float* __restrict__ W,      // [NB, DO, DI]
    float* __restrict__ out)          // [B, SO, N]
{
    __shared__ __align__(16) float Ts[2][DI][36];    // [buf][i][n], pitch 36
    __shared__ __align__(16) float y_s[DO][32];
    const int tid = threadIdx.x;
    const int b  = blockIdx.x >> 5;
    const int n0 = (blockIdx.x & 31) * 32;
    const int op = tid >> 2;          // 0..71 -> o pair (op, op+72)
    const int nq = tid & 3;           // n base = nq*8
    const float* tbase = g_tmp + ((size_t)(b * NPTS + n0)) * NB * DI;

    // prologue: stage k = 0
    for (int idx = tid; idx < 832; idx += TB) {
        int n = idx / 26, q = idx - n * 26;
        float4 v = ((const float4*)(tbase + ((size_t)n * NB) * DI))[q];
        Ts[0][4 * q + 0][n] = v.x; Ts[0][4 * q + 1][n] = v.y;
        Ts[0][4 * q + 2][n] = v.z; Ts[0][4 * q + 3][n] = v.w;
    }
    __syncthreads();

    ull a0[4] = {0, 0, 0, 0}, a1[4] = {0, 0, 0, 0};

    for (int k = 0; k < NB; k++) {
        const int buf = k & 1;
        if (k + 1 < NB) {
            for (int idx = tid; idx < 832; idx += TB) {
                int n = idx / 26, q = idx - n * 26;
                float4 v = ((const float4*)(tbase + ((size_t)n * NB + (k + 1)) * DI))[q];
                Ts[buf ^ 1][4 * q + 0][n] = v.x; Ts[buf ^ 1][4 * q + 1][n] = v.y;
                Ts[buf ^ 1][4 * q + 2][n] = v.z; Ts[buf ^ 1][4 * q + 3][n] = v.w;
            }
        }
        const float4* w0 = (const float4*)(W + ((size_t)k * DO + op) * DI);
        const float4* w1 = (const float4*)(W + ((size_t)k * DO + op + 72) * DI);
#pragma unroll 2
        for (int q = 0; q < 26; q++) {
            float4 wa = w0[q];
            float4 wb = w1[q];
#pragma unroll
            for (int j = 0; j < 4; j++) {
                int i = 4 * q + j;
                F4U t0, t1;
                t0.f = *(const float4*)&Ts[buf][i][nq * 8];
                t1.f = *(const float4*)&Ts[buf][i][nq * 8 + 4];
                float wav = (j == 0) ? wa.x : (j == 1) ? wa.y : (j == 2) ? wa.z : wa.w;
                float wbv = (j == 0) ? wb.x : (j == 1) ? wb.y : (j == 2) ? wb.z : wb.w;
                ull wap = pack2(wav, wav), wbp = pack2(wbv, wbv);
                a0[0] = fma2(t0.u[0], wap, a0[0]);
                a0[1] = fma2(t0.u[1], wap, a0[1]);
                a0[2] = fma2(t1.u[0], wap, a0[2]);
                a0[3] = fma2(t1.u[1], wap, a0[3]);
                a1[0] = fma2(t0.u[0], wbp, a1[0]);
                a1[1] = fma2(t0.u[1], wbp, a1[1]);
                a1[2] = fma2(t1.u[0], wbp, a1[2]);
                a1[3] = fma2(t1.u[1], wbp, a1[3]);
            }
        }
        __syncthreads();
    }

    // spill y to smem
    {
        float v0, v1;
#pragma unroll
        for (int q = 0; q < 4; q++) {
            unpack2(a0[q], v0, v1);
            y_s[op][nq * 8 + 2 * q]     = v0;
            y_s[op][nq * 8 + 2 * q + 1] = v1;
            unpack2(a1[q], v0, v1);
            y_s[op + 72][nq * 8 + 2 * q]     = v0;
            y_s[op + 72][nq * 8 + 2 * q + 1] = v1;
        }
    }
    __syncthreads();

    // gating epilogue
    for (int idx = tid; idx < SO * 32; idx += TB) {
        int cc = idx >> 5, n = idx & 31;
        float v = y_s[cc][n];
        float res;
        if (cc < 32) {
            res = fmaxf(v, 0.0f);
        } else if (cc < 80) {
            int j = (cc - 32) / 3;
            float g = y_s[120 + j][n];
            res = v * __fdividef(1.0f, 1.0f + __expf(-g));
        } else {
            int j = (cc - 80) / 5;
            float g = y_s[136 + j][n];
            res = v * __fdividef(1.0f, 1.0f + __expf(-g));
        }
        out[((size_t)b * SO + cc) * NPTS + n0 + n] = res;
    }
}

// ---------------- launcher ----------------
extern "C" void kernel_launch(void* const* d_in, const int* in_sizes, int n_in,
                              void* d_out, int out_size) {
    (void)in_sizes; (void)n_in; (void)out_size;
    const float* feat = (const float*)d_in[0];
    const float* diff = (const float*)d_in[1];
    const float* mask = (const float*)d_in[2];
    const float* W    = (const float*)d_in[3];

    cudaFuncSetAttribute(se3convA, cudaFuncAttributeMaxDynamicSharedMemorySize, SMEMA_BYTES);

    featSplit<<<(BATCH * 128 * MPTS) / 256, 256>>>(feat);
    se3convA<<<BATCH * (NPTS / 8), 256, SMEMA_BYTES>>>(diff, mask);
    se3convB<<<BATCH * (NPTS / 32), TB>>>(W, (float*)d_out);
}

// round 13
// speedup vs baseline: 3.4419x; 1.1953x over previous
#include <cuda_runtime.h>
#include <cuda_fp16.h>
#include <cstdint>

#define DI    104
#define DO    144
#define SO    120
#define NB    16
#define NPTS  1024
#define MPTS  1024
#define BATCH 4

typedef unsigned long long ull;
typedef unsigned int u32;

// ---------------- device scratch (no allocation) ----------------
__device__ float  g_tmp[(size_t)BATCH * NPTS * NB * DI];   // [b][n][k][i]
__device__ __half g_fh[(size_t)BATCH * 128 * MPTS];        // feat hi fp16, i pad 128
__device__ __half g_fl[(size_t)BATCH * 128 * MPTS];        // feat lo fp16

// ---------------- helpers ----------------
__device__ __forceinline__ u32 smem_u32(const void* p) {
    u32 a;
    asm("{ .reg .u64 t; cvta.to.shared.u64 t, %1; cvt.u32.u64 %0, t; }" : "=r"(a) : "l"(p));
    return a;
}
#define SWZ(o) ((o) ^ (((o) >> 3) & 0x70))

__device__ __forceinline__ ull pack2(float x, float y) {
    ull r; asm("mov.b64 %0, {%1, %2};" : "=l"(r) : "f"(x), "f"(y)); return r;
}
__device__ __forceinline__ void unpack2(ull v, float& x, float& y) {
    asm("mov.b64 {%0, %1}, %2;" : "=f"(x), "=f"(y) : "l"(v));
}
__device__ __forceinline__ ull fma2(ull a, ull b, ull c) {
    ull d; asm("fma.rn.f32x2 %0, %1, %2, %3;" : "=l"(d) : "l"(a), "l"(b), "l"(c));
    return d;
}
union F4U { float4 f; ull u[2]; };

__device__ __forceinline__ void ldsm4(u32& r0, u32& r1, u32& r2, u32& r3, u32 a) {
    asm volatile("ldmatrix.sync.aligned.m8n8.x4.shared.b16 {%0,%1,%2,%3}, [%4];"
        : "=r"(r0), "=r"(r1), "=r"(r2), "=r"(r3) : "r"(a));
}
__device__ __forceinline__ void ldsm2(u32& r0, u32& r1, u32 a) {
    asm volatile("ldmatrix.sync.aligned.m8n8.x2.shared.b16 {%0,%1}, [%2];"
        : "=r"(r0), "=r"(r1) : "r"(a));
}
__device__ __forceinline__ void mma16816h(float* c, const u32* a, const u32* b) {
    asm volatile("mma.sync.aligned.m16n8k16.row.col.f32.f16.f16.f32 "
        "{%0,%1,%2,%3}, {%4,%5,%6,%7}, {%8,%9}, {%0,%1,%2,%3};"
        : "+f"(c[0]), "+f"(c[1]), "+f"(c[2]), "+f"(c[3])
        : "r"(a[0]), "r"(a[1]), "r"(a[2]), "r"(a[3]), "r"(b[0]), "r"(b[1]));
}
__device__ __forceinline__ void sts32(u32 addr, u32 v) {
    asm volatile("st.shared.b32 [%0], %1;" :: "r"(addr), "r"(v));
}
#define CP_ASYNC16(dst, src) \
    asm volatile("cp.async.cg.shared.global [%0], [%1], 16;" :: "r"(dst), "l"(src))
#define CP_COMMIT() asm volatile("cp.async.commit_group;" ::: "memory")
#define CP_WAIT1()  asm volatile("cp.async.wait_group 1;" ::: "memory")

// ---------------- pre-kernel: split features into fp16 hi/lo, pad i to 128 ----------------
__global__ void featSplit(const float* __restrict__ feat) {
    int idx = blockIdx.x * 256 + threadIdx.x;   // B*128*1024 total
    int m = idx & 1023;
    int r = (idx >> 10) & 127;
    int b = idx >> 17;
    float f = (r < DI) ? feat[((size_t)b * DI + r) * MPTS + m] : 0.0f;
    __half h = __float2half_rn(f);
    float lo = f - __half2float(h);
    g_fh[idx] = h;
    g_fl[idx] = __float2half_rn(lo);
}

// ---------------- kernel A: HMMA GEMM  tmp[ch][i] = sum_m phi[ch][m]*feat[i][m] ----------------
// smem: PH [0,16K) ; FH/FL double buffered: buf s at 16K + s*32K (FH), +16K (FL)
#define OFF_PH 0
#define SMEMA_BYTES (16384 + 2 * 32768)

__global__ __launch_bounds__(256, 2) void se3convA(
    const float* __restrict__ diff,   // [B, N, M, 3]
    const float* __restrict__ mask)   // [B, N, M]
{
    extern __shared__ __align__(1024) char smA[];
    const u32 sb = smem_u32(smA);
    const int tid  = threadIdx.x;
    const int lane = tid & 31;
    const int wid  = tid >> 5;
    const int b  = blockIdx.x >> 7;
    const int n0 = (blockIdx.x & 127) * 8;
    const int wm = wid >> 2;    // ch half   (64 rows)
    const int wn = wid & 3;     // i quarter (32 cols)

    // downward chain: multiplier from phi_k to phi_{k-1} = w * exp((64/225)(2k-1)),
    // k = 15..1 decreasing: seed exp((64/225)*29), decay exp(-128/225).
    const float CTOP = __expf(8.2488890f);
    const float CDEC = __expf(-0.5688889f);

    float c[4][4][4];
#pragma unroll
    for (int mt = 0; mt < 4; mt++)
#pragma unroll
        for (int nb = 0; nb < 4; nb++)
#pragma unroll
            for (int q = 0; q < 4; q++) c[mt][nb][q] = 0.0f;

    const int pn  = wid;        // n handled by this warp (phi producer)
    const int pm0 = lane;       // m-pair index
    const float* diff_p = diff + ((size_t)(b * NPTS + n0 + pn)) * MPTS * 3;
    const float* mask_p = mask + ((size_t)(b * NPTS + n0 + pn)) * MPTS;
    const uint4* fh_g = (const uint4*)(g_fh + (size_t)b * 128 * MPTS);  // 128 uint4/row
    const uint4* fl_g = (const uint4*)(g_fl + (size_t)b * 128 * MPTS);

    const u32 aRow  = (u32)(lane & 15);
    const u32 aColB = (u32)((lane >> 4) * 16);
    const u32 bRow  = (u32)(lane & 7);
    const u32 bColB = (u32)(((lane >> 3) & 1) * 16);

    // per-thread staging slots (same every chunk)
    const int sr = tid >> 3, sj = tid & 7;          // rows tid/8 stepped by 32
    // prologue: cp.async chunk 0 into buf 0
    {
        const u32 fb = sb + 16384;
#pragma unroll
        for (int t = 0; t < 4; t++) {
            int r = sr + t * 32;
            u32 sw = SWZ((u32)(r * 128 + sj * 16));
            CP_ASYNC16(fb + sw,         fh_g + r * 128 + sj);
            CP_ASYNC16(fb + 16384 + sw, fl_g + r * 128 + sj);
        }
        CP_COMMIT();
    }

    for (int cc = 0; cc < 16; cc++) {
        const u32 fbase = sb + 16384 + (u32)(cc & 1) * 32768;

        // --- phi [128 ch][64 m] single fp16: 2 m per thread, downward chain ---
        {
            const int m = cc * 64 + 2 * pm0;
            const float2* dp = (const float2*)(diff_p + (size_t)3 * m);
            float2 d0 = dp[0], d1 = dp[1], d2 = dp[2];
            float2 mk = *(const float2*)(mask_p + m);
            float r2a = fmaf(d0.x, d0.x, fmaf(d0.y, d0.y, fmaf(d1.x, d1.x, 1e-12f)));
            float r2b = fmaf(d1.y, d1.y, fmaf(d2.x, d2.x, fmaf(d2.y, d2.y, 1e-12f)));
            float ra = r2a * rsqrtf(r2a);
            float rb = r2b * rsqrtf(r2b);
            float ea = ra - 2.0f, eb = rb - 2.0f;
            float pa = __expf(-16.0f * ea * ea) * mk.x;     // phi_15 * mask
            float pb = __expf(-16.0f * eb * eb) * mk.y;
            float wa = __expf(-4.26666667f * ra);
            float wb = __expf(-4.26666667f * rb);
            float ua = wa * CTOP;
            float ub = wb * CTOP;
            const u32 colb = 4u * (u32)pm0;
#pragma unroll
            for (int k = 15; k >= 0; k--) {
                u32 hp;
                asm("cvt.rn.f16x2.f32 %0, %1, %2;" : "=r"(hp) : "f"(pb), "f"(pa));
                u32 off = SWZ((u32)((pn * 16 + k) * 128) + colb);
                sts32(sb + OFF_PH + off, hp);
                if (k > 0) { pa *= ua; pb *= ub; ua *= CDEC; ub *= CDEC; }
            }
        }

        // --- prefetch chunk cc+1 into the other buffer ---
        if (cc < 15) {
            const u32 fb = sb + 16384 + (u32)((cc + 1) & 1) * 32768;
            const int col0 = 8 * (cc + 1);
#pragma unroll
            for (int t = 0; t < 4; t++) {
                int r = sr + t * 32;
                u32 sw = SWZ((u32)(r * 128 + sj * 16));
                CP_ASYNC16(fb + sw,         fh_g + r * 128 + col0 + sj);
                CP_ASYNC16(fb + 16384 + sw, fl_g + r * 128 + col0 + sj);
            }
        }
        CP_COMMIT();
        CP_WAIT1();       // chunk cc's feat tiles landed
        __syncthreads();  // + phi stores visible

        // --- MMA: 4 k-steps, 2 products (p*fh + p*fl) into fp32 acc ---
#pragma unroll
        for (int ks = 0; ks < 4; ks++) {
            const u32 mb = (u32)(ks * 32);
            u32 ap[4][4], bh[4][2], bl[4][2];
#pragma unroll
            for (int mt = 0; mt < 4; mt++) {
                u32 row = (u32)(wm * 64 + mt * 16) + aRow;
                u32 off = SWZ(row * 128 + mb + aColB);
                ldsm4(ap[mt][0], ap[mt][1], ap[mt][2], ap[mt][3], sb + OFF_PH + off);
            }
#pragma unroll
            for (int nb = 0; nb < 4; nb++) {
                u32 row = (u32)(wn * 32 + nb * 8) + bRow;
                u32 off = SWZ(row * 128 + mb + bColB);
                ldsm2(bh[nb][0], bh[nb][1], fbase + off);
                ldsm2(bl[nb][0], bl[nb][1], fbase + 16384 + off);
            }
#pragma unroll
            for (int mt = 0; mt < 4; mt++)
#pragma unroll
                for (int nb = 0; nb < 4; nb++) {
                    mma16816h(c[mt][nb], ap[mt], bh[nb]);   // p*fh
                    mma16816h(c[mt][nb], ap[mt], bl[nb]);   // p*fl
                }
        }
        __syncthreads();   // PH consumed; next chunk may overwrite
    }

    // --- store C: rows ch (i contiguous), coalesced float2 ---
    const size_t obase = ((size_t)(b * NPTS + n0)) * NB * DI;
#pragma unroll
    for (int mt = 0; mt < 4; mt++) {
        int ch0 = wm * 64 + mt * 16 + (lane >> 2);
        float* r0 = g_tmp + obase + (size_t)ch0 * DI;
#pragma unroll
        for (int nb = 0; nb < 4; nb++) {
            int i0 = wn * 32 + nb * 8 + (lane & 3) * 2;
            if (i0 < DI) {
                *(float2*)(r0 + i0)          = make_float2(c[mt][nb][0], c[mt][nb][1]);
                *(float2*)(r0 + 8 * DI + i0) = make_float2(c[mt][nb][2], c[mt][nb][3]);
            }
        }
    }
}

// ---------------- kernel B: y = W x tmp (FFMA2) + gating epilogue ----------------
// 256 CTAs, 16 n each; thread = (o-pair op/op+72, n-quad nq*4)
#define TB 288

__global__ __launch_bounds__(TB, 2) void se3convB(
    const float* __restrict__ W,      // [NB, DO, DI]
    float* __restrict__ out)          // [B, SO, N]
{
    __shared__ __align__(16) float Ts[2][DI][20];    // [buf][i][n], pitch 20
    __shared__ __align__(16) float y_s[DO][16];
    const int tid = threadIdx.x;
    const int b  = blockIdx.x >> 6;
    const int n0 = (blockIdx.x & 63) * 16;
    const int op = tid >> 2;          // 0..71 -> o pair (op, op+72)
    const int nq = tid & 3;           // n base = nq*4
    const float* tbase = g_tmp + ((size_t)(b * NPTS + n0)) * NB * DI;

    // prologue: stage k = 0 (16 n x 26 float4)
    for (int idx = tid; idx < 416; idx += TB) {
        int n = idx / 26, q = idx - n * 26;
        float4 v = ((const float4*)(tbase + ((size_t)n * NB) * DI))[q];
        Ts[0][4 * q + 0][n] = v.x; Ts[0][4 * q + 1][n] = v.y;
        Ts[0][4 * q + 2][n] = v.z; Ts[0][4 * q + 3][n] = v.w;
    }
    __syncthreads();

    ull a0[2] = {0, 0}, a1[2] = {0, 0};

    for (int k = 0; k < NB; k++) {
        const int buf = k & 1;
        if (k + 1 < NB) {
            for (int idx = tid; idx < 416; idx += TB) {
                int n = idx / 26, q = idx - n * 26;
                float4 v = ((const float4*)(tbase + ((size_t)n * NB + (k + 1)) * DI))[q];
                Ts[buf ^ 1][4 * q + 0][n] = v.x; Ts[buf ^ 1][4 * q + 1][n] = v.y;
                Ts[buf ^ 1][4 * q + 2][n] = v.z; Ts[buf ^ 1][4 * q + 3][n] = v.w;
            }
        }
        const float4* w0 = (const float4*)(W + ((size_t)k * DO + op) * DI);
        const float4* w1 = (const float4*)(W + ((size_t)k * DO + op + 72) * DI);
#pragma unroll 2
        for (int q = 0; q < 26; q++) {
            float4 wa = w0[q];
            float4 wb = w1[q];
#pragma unroll
            for (int j = 0; j < 4; j++) {
                int i = 4 * q + j;
                F4U t;
                t.f = *(const float4*)&Ts[buf][i][nq * 4];
                float wav = (j == 0) ? wa.x : (j == 1) ? wa.y : (j == 2) ? wa.z : wa.w;
                float wbv = (j == 0) ? wb.x : (j == 1) ? wb.y : (j == 2) ? wb.z : wb.w;
                ull wap = pack2(wav, wav), wbp = pack2(wbv, wbv);
                a0[0] = fma2(t.u[0], wap, a0[0]);
                a0[1] = fma2(t.u[1], wap, a0[1]);
                a1[0] = fma2(t.u[0], wbp, a1[0]);
                a1[1] = fma2(t.u[1], wbp, a1[1]);
            }
        }
        __syncthreads();
    }

    // spill y to smem
    {
        float v0, v1;
#pragma unroll
        for (int q = 0; q < 2; q++) {
            unpack2(a0[q], v0, v1);
            y_s[op][nq * 4 + 2 * q]     = v0;
            y_s[op][nq * 4 + 2 * q + 1] = v1;
            unpack2(a1[q], v0, v1);
            y_s[op + 72][nq * 4 + 2 * q]     = v0;
            y_s[op + 72][nq * 4 + 2 * q + 1] = v1;
        }
    }
    __syncthreads();

    // gating epilogue (SO*16 = 1920 elements)
    for (int idx = tid; idx < SO * 16; idx += TB) {
        int cc = idx >> 4, n = idx & 15;
        float v = y_s[cc][n];
        float res;
        if (cc < 32) {
            res = fmaxf(v, 0.0f);
        } else if (cc < 80) {
            int j = (cc - 32) / 3;
            float g = y_s[120 + j][n];
            res = v * __fdividef(1.0f, 1.0f + __expf(-g));
        } else {
            int j = (cc - 80) / 5;
            float g = y_s[136 + j][n];
            res = v * __fdividef(1.0f, 1.0f + __expf(-g));
        }
        out[((size_t)b * SO + cc) * NPTS + n0 + n] = res;
    }
}

// ---------------- launcher ----------------
extern "C" void kernel_launch(void* const* d_in, const int* in_sizes, int n_in,
                              void* d_out, int out_size) {
    (void)in_sizes; (void)n_in; (void)out_size;
    const float* feat = (const float*)d_in[0];
    const float* diff = (const float*)d_in[1];
    const float* mask = (const float*)d_in[2];
    const float* W    = (const float*)d_in[3];

    cudaFuncSetAttribute(se3convA, cudaFuncAttributeMaxDynamicSharedMemorySize, SMEMA_BYTES);

    featSplit<<<(BATCH * 128 * MPTS) / 256, 256>>>(feat);
    se3convA<<<BATCH * (NPTS / 8), 256, SMEMA_BYTES>>>(diff, mask);
    se3convB<<<BATCH * (NPTS / 16), TB>>>(W, (float*)d_out);
}

// round 16
// speedup vs baseline: 4.1751x; 1.2130x over previous
#include <cuda_runtime.h>
#include <cuda_fp16.h>
#include <cstdint>

#define DI    104
#define DO    144
#define SO    120
#define NB    16
#define NPTS  1024
#define MPTS  1024
#define BATCH 4

typedef unsigned long long ull;
typedef unsigned int u32;

// ---------------- device scratch (no allocation) ----------------
__device__ float  g_tmp[(size_t)BATCH * NPTS * NB * DI];   // [b][n][k][i]
__device__ __half g_fh[(size_t)BATCH * 128 * MPTS];        // feat fp16, i pad 128

// ---------------- helpers ----------------
__device__ __forceinline__ u32 smem_u32(const void* p) {
    u32 a;
    asm("{ .reg .u64 t; cvta.to.shared.u64 t, %1; cvt.u32.u64 %0, t; }" : "=r"(a) : "l"(p));
    return a;
}
#define SWZ(o) ((o) ^ (((o) >> 3) & 0x70))

__device__ __forceinline__ ull pack2(float x, float y) {
    ull r; asm("mov.b64 %0, {%1, %2};" : "=l"(r) : "f"(x), "f"(y)); return r;
}
__device__ __forceinline__ void unpack2(ull v, float& x, float& y) {
    asm("mov.b64 {%0, %1}, %2;" : "=f"(x), "=f"(y) : "l"(v));
}
__device__ __forceinline__ ull fma2(ull a, ull b, ull c) {
    ull d; asm("fma.rn.f32x2 %0, %1, %2, %3;" : "=l"(d) : "l"(a), "l"(b), "l"(c));
    return d;
}
union F4U { float4 f; ull u[2]; };

__device__ __forceinline__ void ldsm4(u32& r0, u32& r1, u32& r2, u32& r3, u32 a) {
    asm volatile("ldmatrix.sync.aligned.m8n8.x4.shared.b16 {%0,%1,%2,%3}, [%4];"
        : "=r"(r0), "=r"(r1), "=r"(r2), "=r"(r3) : "r"(a));
}
__device__ __forceinline__ void ldsm2(u32& r0, u32& r1, u32 a) {
    asm volatile("ldmatrix.sync.aligned.m8n8.x2.shared.b16 {%0,%1}, [%2];"
        : "=r"(r0), "=r"(r1) : "r"(a));
}
__device__ __forceinline__ void mma16816h(float* c, const u32* a, const u32* b) {
    asm volatile("mma.sync.aligned.m16n8k16.row.col.f32.f16.f16.f32 "
        "{%0,%1,%2,%3}, {%4,%5,%6,%7}, {%8,%9}, {%0,%1,%2,%3};"
        : "+f"(c[0]), "+f"(c[1]), "+f"(c[2]), "+f"(c[3])
        : "r"(a[0]), "r"(a[1]), "r"(a[2]), "r"(a[3]), "r"(b[0]), "r"(b[1]));
}
__device__ __forceinline__ void sts32(u32 addr, u32 v) {
    asm volatile("st.shared.b32 [%0], %1;" :: "r"(addr), "r"(v));
}
#define CP_ASYNC16(dst, src) \
    asm volatile("cp.async.cg.shared.global [%0], [%1], 16;" :: "r"(dst), "l"(src))
#define CP_COMMIT() asm volatile("cp.async.commit_group;" ::: "memory")
#define CP_WAIT1()  asm volatile("cp.async.wait_group 1;" ::: "memory")

// ---------------- pre-kernel: features -> fp16, pad i to 128 ----------------
__global__ void featSplit(const float* __restrict__ feat) {
    int idx = blockIdx.x * 256 + threadIdx.x;   // B*128*1024 total
    int m = idx & 1023;
    int r = (idx >> 10) & 127;
    int b = idx >> 17;
    float f = (r < DI) ? feat[((size_t)b * DI + r) * MPTS + m] : 0.0f;
    g_fh[idx] = __float2half_rn(f);
}

// ---------------- kernel A: HMMA GEMM  tmp[ch][i] = sum_m phi[ch][m]*feat[i][m] ----------------
// smem: PH [0,16K) ; FH double buffered at 16K + s*16K
#define OFF_PH 0
#define SMEMA_BYTES (16384 + 2 * 16384)

__global__ __launch_bounds__(256, 2) void se3convA(
    const float* __restrict__ diff,   // [B, N, M, 3]
    const float* __restrict__ mask)   // [B, N, M]
{
    extern __shared__ __align__(1024) char smA[];
    const u32 sb = smem_u32(smA);
    const int tid  = threadIdx.x;
    const int lane = tid & 31;
    const int wid  = tid >> 5;
    const int b  = blockIdx.x >> 7;
    const int n0 = (blockIdx.x & 127) * 8;
    const int wm = wid >> 2;    // ch half   (64 rows)
    const int wn = wid & 3;     // i quarter (32 cols)

    // downward chain: multiplier phi_k -> phi_{k-1} = w * exp((64/225)(2k-1)),
    // decreasing for k = 15..1: seed exp((64/225)*29), decay exp(-128/225).
    const float CTOP = __expf(8.2488890f);
    const float CDEC = __expf(-0.5688889f);

    float c[4][4][4];
#pragma unroll
    for (int mt = 0; mt < 4; mt++)
#pragma unroll
        for (int nb = 0; nb < 4; nb++)
#pragma unroll
            for (int q = 0; q < 4; q++) c[mt][nb][q] = 0.0f;

    const int pn  = wid;        // n handled by this warp (phi producer)
    const int pm0 = lane;       // m-pair index
    const float* diff_p = diff + ((size_t)(b * NPTS + n0 + pn)) * MPTS * 3;
    const float* mask_p = mask + ((size_t)(b * NPTS + n0 + pn)) * MPTS;
    const uint4* fh_g = (const uint4*)(g_fh + (size_t)b * 128 * MPTS);  // 128 uint4/row

    const u32 aRow  = (u32)(lane & 15);
    const u32 aColB = (u32)((lane >> 4) * 16);
    const u32 bRow  = (u32)(lane & 7);
    const u32 bColB = (u32)(((lane >> 3) & 1) * 16);

    // per-thread staging slots
    const int sr = tid >> 3, sj = tid & 7;
    // prologue: cp.async chunk 0 into buf 0
    {
        const u32 fb = sb + 16384;
#pragma unroll
        for (int t = 0; t < 4; t++) {
            int r = sr + t * 32;
            u32 sw = SWZ((u32)(r * 128 + sj * 16));
            CP_ASYNC16(fb + sw, fh_g + r * 128 + sj);
        }
        CP_COMMIT();
    }

    for (int cc = 0; cc < 16; cc++) {
        const u32 fbase = sb + 16384 + (u32)(cc & 1) * 16384;

        // --- phi [128 ch][64 m] fp16: 2 m per thread, downward chain ---
        {
            const int m = cc * 64 + 2 * pm0;
            const float2* dp = (const float2*)(diff_p + (size_t)3 * m);
            float2 d0 = dp[0], d1 = dp[1], d2 = dp[2];
            float2 mk = *(const float2*)(mask_p + m);
            float r2a = fmaf(d0.x, d0.x, fmaf(d0.y, d0.y, fmaf(d1.x, d1.x, 1e-12f)));
            float r2b = fmaf(d1.y, d1.y, fmaf(d2.x, d2.x, fmaf(d2.y, d2.y, 1e-12f)));
            float ra = r2a * rsqrtf(r2a);
            float rb = r2b * rsqrtf(r2b);
            float ea = ra - 2.0f, eb = rb - 2.0f;
            float pa = __expf(-16.0f * ea * ea) * mk.x;     // phi_15 * mask
            float pb = __expf(-16.0f * eb * eb) * mk.y;
            float wa = __expf(-4.26666667f * ra);
            float wb = __expf(-4.26666667f * rb);
            float ua = wa * CTOP;
            float ub = wb * CTOP;
            const u32 colb = 4u * (u32)pm0;
#pragma unroll
            for (int k = 15; k >= 0; k--) {
                u32 hp;
                asm("cvt.rn.f16x2.f32 %0, %1, %2;" : "=r"(hp) : "f"(pb), "f"(pa));
                u32 off = SWZ((u32)((pn * 16 + k) * 128) + colb);
                sts32(sb + OFF_PH + off, hp);
                if (k > 0) { pa *= ua; pb *= ub; ua *= CDEC; ub *= CDEC; }
            }
        }

        // --- prefetch chunk cc+1 into the other buffer ---
        if (cc < 15) {
            const u32 fb = sb + 16384 + (u32)((cc + 1) & 1) * 16384;
            const int col0 = 8 * (cc + 1);
#pragma unroll
            for (int t = 0; t < 4; t++) {
                int r = sr + t * 32;
                u32 sw = SWZ((u32)(r * 128 + sj * 16));
                CP_ASYNC16(fb + sw, fh_g + r * 128 + col0 + sj);
            }
        }
        CP_COMMIT();
        CP_WAIT1();       // chunk cc's feat tile landed
        __syncthreads();  // + phi stores visible

        // --- MMA: 4 k-steps, single product p*f into fp32 acc ---
#pragma unroll
        for (int ks = 0; ks < 4; ks++) {
            const u32 mb = (u32)(ks * 32);
            u32 ap[4][4], bh[4][2];
#pragma unroll
            for (int mt = 0; mt < 4; mt++) {
                u32 row = (u32)(wm * 64 + mt * 16) + aRow;
                u32 off = SWZ(row * 128 + mb + aColB);
                ldsm4(ap[mt][0], ap[mt][1], ap[mt][2], ap[mt][3], sb + OFF_PH + off);
            }
#pragma unroll
            for (int nb = 0; nb < 4; nb++) {
                u32 row = (u32)(wn * 32 + nb * 8) + bRow;
                u32 off = SWZ(row * 128 + mb + bColB);
                ldsm2(bh[nb][0], bh[nb][1], fbase + off);
            }
#pragma unroll
            for (int mt = 0; mt < 4; mt++)
#pragma unroll
                for (int nb = 0; nb < 4; nb++)
                    mma16816h(c[mt][nb], ap[mt], bh[nb]);
        }
        __syncthreads();   // PH consumed; next chunk may overwrite
    }

    // --- store C: rows ch (i contiguous), coalesced float2 ---
    const size_t obase = ((size_t)(b * NPTS + n0)) * NB * DI;
#pragma unroll
    for (int mt = 0; mt < 4; mt++) {
        int ch0 = wm * 64 + mt * 16 + (lane >> 2);
        float* r0 = g_tmp + obase + (size_t)ch0 * DI;
#pragma unroll
        for (int nb = 0; nb < 4; nb++) {
            int i0 = wn * 32 + nb * 8 + (lane & 3) * 2;
            if (i0 < DI) {
                *(float2*)(r0 + i0)          = make_float2(c[mt][nb][0], c[mt][nb][1]);
                *(float2*)(r0 + 8 * DI + i0) = make_float2(c[mt][nb][2], c[mt][nb][3]);
            }
        }
    }
}

// ---------------- kernel B: y = W x tmp (FFMA2) + gating epilogue ----------------
#define TB 288

__global__ __launch_bounds__(TB, 2) void se3convB(
    const float* __restrict__ W,      // [NB, DO, DI]
    float* __restrict__ out)          // [B, SO, N]
{
    __shared__ __align__(16) float Ts[2][DI][20];    // [buf][i][n], pitch 20
    __shared__ __align__(16) float y_s[DO][16];
    const int tid = threadIdx.x;
    const int b  = blockIdx.x >> 6;
    const int n0 = (blockIdx.x & 63) * 16;
    const int op = tid >> 2;          // 0..71 -> o pair (op, op+72)
    const int nq = tid & 3;           // n base = nq*4
    const float* tbase = g_tmp + ((size_t)(b * NPTS + n0)) * NB * DI;

    // prologue: stage k = 0 (16 n x 26 float4)
    for (int idx = tid; idx < 416; idx += TB) {
        int n = idx / 26, q = idx - n * 26;
        float4 v = ((const float4*)(tbase + ((size_t)n * NB) * DI))[q];
        Ts[0][4 * q + 0][n] = v.x; Ts[0][4 * q + 1][n] = v.y;
        Ts[0][4 * q + 2][n] = v.z; Ts[0][4 * q + 3][n] = v.w;
    }
    __syncthreads();

    ull a0[2] = {0, 0}, a1[2] = {0, 0};

    for (int k = 0; k < NB; k++) {
        const int buf = k & 1;
        if (k + 1 < NB) {
            for (int idx = tid; idx < 416; idx += TB) {
                int n = idx / 26, q = idx - n * 26;
                float4 v = ((const float4*)(tbase + ((size_t)n * NB + (k + 1)) * DI))[q];
                Ts[buf ^ 1][4 * q + 0][n] = v.x; Ts[buf ^ 1][4 * q + 1][n] = v.y;
                Ts[buf ^ 1][4 * q + 2][n] = v.z; Ts[buf ^ 1][4 * q + 3][n] = v.w;
            }
        }
        const float4* w0 = (const float4*)(W + ((size_t)k * DO + op) * DI);
        const float4* w1 = (const float4*)(W + ((size_t)k * DO + op + 72) * DI);
#pragma unroll 2
        for (int q = 0; q < 26; q++) {
            float4 wa = w0[q];
            float4 wb = w1[q];
#pragma unroll
            for (int j = 0; j < 4; j++) {
                int i = 4 * q + j;
                F4U t;
                t.f = *(const float4*)&Ts[buf][i][nq * 4];
                float wav = (j == 0) ? wa.x : (j == 1) ? wa.y : (j == 2) ? wa.z : wa.w;
                float wbv = (j == 0) ? wb.x : (j == 1) ? wb.y : (j == 2) ? wb.z : wb.w;
                ull wap = pack2(wav, wav), wbp = pack2(wbv, wbv);
                a0[0] = fma2(t.u[0], wap, a0[0]);
                a0[1] = fma2(t.u[1], wap, a0[1]);
                a1[0] = fma2(t.u[0], wbp, a1[0]);
                a1[1] = fma2(t.u[1], wbp, a1[1]);
            }
        }
        __syncthreads();
    }

    // spill y to smem
    {
        float v0, v1;
#pragma unroll
        for (int q = 0; q < 2; q++) {
            unpack2(a0[q], v0, v1);
            y_s[op][nq * 4 + 2 * q]     = v0;
            y_s[op][nq * 4 + 2 * q + 1] = v1;
            unpack2(a1[q], v0, v1);
            y_s[op + 72][nq * 4 + 2 * q]     = v0;
            y_s[op + 72][nq * 4 + 2 * q + 1] = v1;
        }
    }
    __syncthreads();

    // gating epilogue (SO*16 = 1920 elements)
    for (int idx = tid; idx < SO * 16; idx += TB) {
        int cc = idx >> 4, n = idx & 15;
        float v = y_s[cc][n];
        float res;
        if (cc < 32) {
            res = fmaxf(v, 0.0f);
        } else if (cc < 80) {
            int j = (cc - 32) / 3;
            float g = y_s[120 + j][n];
            res = v * __fdividef(1.0f, 1.0f + __expf(-g));
        } else {
            int j = (cc - 80) / 5;
            float g = y_s[136 + j][n];
            res = v * __fdividef(1.0f, 1.0f + __expf(-g));
        }
        out[((size_t)b * SO + cc) * NPTS + n0 + n] = res;
    }
}

// ---------------- launcher ----------------
extern "C" void kernel_launch(void* const* d_in, const int* in_sizes, int n_in,
                              void* d_out, int out_size) {
    (void)in_sizes; (void)n_in; (void)out_size;
    const float* feat = (const float*)d_in[0];
    const float* diff = (const float*)d_in[1];
    const float* mask = (const float*)d_in[2];
    const float* W    = (const float*)d_in[3];

    cudaFuncSetAttribute(se3convA, cudaFuncAttributeMaxDynamicSharedMemorySize, SMEMA_BYTES);

    featSplit<<<(BATCH * 128 * MPTS) / 256, 256>>>(feat);
    se3convA<<<BATCH * (NPTS / 8), 256, SMEMA_BYTES>>>(diff, mask);
    se3convB<<<BATCH * (NPTS / 16), TB>>>(W, (float*)d_out);
}

// round 17
// speedup vs baseline: 4.1873x; 1.0029x over previous
#include <cuda_runtime.h>
#include <cuda_fp16.h>
#include <cstdint>

#define DI    104
#define DO    144
#define SO    120
#define NB    16
#define NPTS  1024
#define MPTS  1024
#define BATCH 4

typedef unsigned long long ull;
typedef unsigned int u32;

// ---------------- device scratch (no allocation) ----------------
__device__ float  g_tmp[(size_t)BATCH * NPTS * NB * DI];   // [b][n][k][i]
__device__ __half g_fh[(size_t)BATCH * 128 * MPTS];        // feat fp16, i pad 128

// ---------------- helpers ----------------
__device__ __forceinline__ u32 smem_u32(const void* p) {
    u32 a;
    asm("{ .reg .u64 t; cvta.to.shared.u64 t, %1; cvt.u32.u64 %0, t; }" : "=r"(a) : "l"(p));
    return a;
}
#define SWZ(o) ((o) ^ (((o) >> 3) & 0x70))
// phi tile [64 m][128 ch] fp16, 256B rows: 16B-col XOR with (m&7)
__device__ __forceinline__ u32 swzT(u32 m, u32 c16) {
    return m * 256 + ((c16 ^ (m & 7)) << 4);
}

__device__ __forceinline__ ull pack2(float x, float y) {
    ull r; asm("mov.b64 %0, {%1, %2};" : "=l"(r) : "f"(x), "f"(y)); return r;
}
__device__ __forceinline__ void unpack2(ull v, float& x, float& y) {
    asm("mov.b64 {%0, %1}, %2;" : "=f"(x), "=f"(y) : "l"(v));
}
__device__ __forceinline__ ull fma2(ull a, ull b, ull c) {
    ull d; asm("fma.rn.f32x2 %0, %1, %2, %3;" : "=l"(d) : "l"(a), "l"(b), "l"(c));
    return d;
}
union F4U { float4 f; ull u[2]; };

__device__ __forceinline__ void ldsm4t(u32& r0, u32& r1, u32& r2, u32& r3, u32 a) {
    asm volatile("ldmatrix.sync.aligned.m8n8.x4.trans.shared.b16 {%0,%1,%2,%3}, [%4];"
        : "=r"(r0), "=r"(r1), "=r"(r2), "=r"(r3) : "r"(a));
}
__device__ __forceinline__ void ldsm2(u32& r0, u32& r1, u32 a) {
    asm volatile("ldmatrix.sync.aligned.m8n8.x2.shared.b16 {%0,%1}, [%2];"
        : "=r"(r0), "=r"(r1) : "r"(a));
}
__device__ __forceinline__ void mma16816h(float* c, const u32* a, const u32* b) {
    asm volatile("mma.sync.aligned.m16n8k16.row.col.f32.f16.f16.f32 "
        "{%0,%1,%2,%3}, {%4,%5,%6,%7}, {%8,%9}, {%0,%1,%2,%3};"
        : "+f"(c[0]), "+f"(c[1]), "+f"(c[2]), "+f"(c[3])
        : "r"(a[0]), "r"(a[1]), "r"(a[2]), "r"(a[3]), "r"(b[0]), "r"(b[1]));
}
__device__ __forceinline__ void sts128(u32 addr, u32 x, u32 y, u32 z, u32 w) {
    asm volatile("st.shared.v4.b32 [%0], {%1,%2,%3,%4};"
        :: "r"(addr), "r"(x), "r"(y), "r"(z), "r"(w));
}
// cvt: first operand -> HIGH half, second -> LOW half
__device__ __forceinline__ u32 cvt2h(float hi, float lo) {
    u32 d; asm("cvt.rn.f16x2.f32 %0, %1, %2;" : "=r"(d) : "f"(hi), "f"(lo));
    return d;
}
#define CP_ASYNC16(dst, src) \
    asm volatile("cp.async.cg.shared.global [%0], [%1], 16;" :: "r"(dst), "l"(src))
#define CP_COMMIT() asm volatile("cp.async.commit_group;" ::: "memory")
#define CP_WAIT1()  asm volatile("cp.async.wait_group 1;" ::: "memory")

// ---------------- pre-kernel: features -> fp16, pad i to 128 ----------------
__global__ void featSplit(const float* __restrict__ feat) {
    int idx = blockIdx.x * 256 + threadIdx.x;   // B*128*1024 total
    int m = idx & 1023;
    int r = (idx >> 10) & 127;
    int b = idx >> 17;
    float f = (r < DI) ? feat[((size_t)b * DI + r) * MPTS + m] : 0.0f;
    g_fh[idx] = __float2half_rn(f);
}

// ---------------- kernel A: HMMA GEMM  tmp[ch][i] = sum_m phi[ch][m]*feat[i][m] ----------------
// smem: PHI-T [0,16K) ([64 m][128 ch] fp16) ; FH double buffered at 16K + s*16K (SW128 [i][m])
#define OFF_PH 0
#define SMEMA_BYTES (16384 + 2 * 16384)

__global__ __launch_bounds__(256, 2) void se3convA(
    const float* __restrict__ diff,   // [B, N, M, 3]
    const float* __restrict__ mask)   // [B, N, M]
{
    extern __shared__ __align__(1024) char smA[];
    const u32 sb = smem_u32(smA);
    const int tid  = threadIdx.x;
    const int lane = tid & 31;
    const int wid  = tid >> 5;
    const int b  = blockIdx.x >> 7;
    const int n0 = (blockIdx.x & 127) * 8;
    const int wm = wid >> 2;    // ch half   (64 rows)
    const int wn = wid & 3;     // i quarter (32 cols)

    // downward chain: phi_k -> phi_{k-1} multiplier = w * exp((64/225)(2k-1)),
    // decreasing for k = 15..1: seed exp((64/225)*29), decay exp(-128/225).
    const float CTOP = __expf(8.2488890f);
    const float CDEC = __expf(-0.5688889f);

    float c[4][4][4];
#pragma unroll
    for (int mt = 0; mt < 4; mt++)
#pragma unroll
        for (int nb = 0; nb < 4; nb++)
#pragma unroll
            for (int q = 0; q < 4; q++) c[mt][nb][q] = 0.0f;

    const int pn = wid;         // n handled by this warp (phi producer): ch rows pn*16+k
    const float* diff_p = diff + ((size_t)(b * NPTS + n0 + pn)) * MPTS * 3;
    const float* mask_p = mask + ((size_t)(b * NPTS + n0 + pn)) * MPTS;
    const uint4* fh_g = (const uint4*)(g_fh + (size_t)b * 128 * MPTS);  // 128 uint4/row

    // feat (B-operand) ldmatrix lane addressing
    const u32 bRow  = (u32)(lane & 7);
    const u32 bColB = (u32)(((lane >> 3) & 1) * 16);
    // phi (A-operand, transposed tile) ldmatrix.trans lane addressing
    const u32 tRowL = (u32)((lane & 7) + ((lane >> 4) << 3));   // + ks*16
    const u32 tC16L = (u32)((lane >> 3) & 1);                   // + wm*8 + mt*2

    // per-thread cp.async staging slots
    const int sr = tid >> 3, sj = tid & 7;
    {
        const u32 fb = sb + 16384;
#pragma unroll
        for (int t = 0; t < 4; t++) {
            int r = sr + t * 32;
            u32 sw = SWZ((u32)(r * 128 + sj * 16));
            CP_ASYNC16(fb + sw, fh_g + r * 128 + sj);
        }
        CP_COMMIT();
    }

    for (int cc = 0; cc < 16; cc++) {
        const u32 fbase = sb + 16384 + (u32)(cc & 1) * 16384;

        // --- phi tile [64 m][128 ch] fp16: thread owns m = lane, lane+32; ch = pn*16..+15 ---
        {
            const int mA = cc * 64 + lane;        // global m for chain A
            const int mB = mA + 32;
            float dax = diff_p[3 * mA], day = diff_p[3 * mA + 1], daz = diff_p[3 * mA + 2];
            float dbx = diff_p[3 * mB], dby = diff_p[3 * mB + 1], dbz = diff_p[3 * mB + 2];
            float mka = mask_p[mA], mkb = mask_p[mB];
            float r2a = fmaf(dax, dax, fmaf(day, day, fmaf(daz, daz, 1e-12f)));
            float r2b = fmaf(dbx, dbx, fmaf(dby, dby, fmaf(dbz, dbz, 1e-12f)));
            float ra = r2a * rsqrtf(r2a);
            float rb = r2b * rsqrtf(r2b);
            float ea = ra - 2.0f, eb = rb - 2.0f;
            float pa = __expf(-16.0f * ea * ea) * mka;   // phi_15 * mask
            float pb = __expf(-16.0f * eb * eb) * mkb;
            float wa = __expf(-4.26666667f * ra);
            float wb = __expf(-4.26666667f * rb);
            float ua = wa * CTOP;
            float ub = wb * CTOP;

            const u32 rA = (u32)lane;           // local m row
            const u32 rB = (u32)(lane + 32);
            const u32 c16lo = (u32)(pn * 2);    // ch k=0..7
            const u32 c16hi = c16lo + 1;        // ch k=8..15

            u32 qa[4], qb[4];
            float prA = 0.0f, prB = 0.0f;
#pragma unroll
            for (int k = 15; k >= 0; k--) {
                if (k & 1) {
                    prA = pa; prB = pb;
                } else {
                    int s = (k >> 1) & 3;       // slot within 4-pair group
                    qa[s] = cvt2h(prA, pa);     // (lo = phi_k, hi = phi_{k+1})
                    qb[s] = cvt2h(prB, pb);
                    if (k == 8) {               // pairs k8..15 ready -> c16hi
                        sts128(sb + OFF_PH + swzT(rA, c16hi), qa[0], qa[1], qa[2], qa[3]);
                        sts128(sb + OFF_PH + swzT(rB, c16hi), qb[0], qb[1], qb[2], qb[3]);
                    } else if (k == 0) {        // pairs k0..7 -> c16lo
                        sts128(sb + OFF_PH + swzT(rA, c16lo), qa[0], qa[1], qa[2], qa[3]);
                        sts128(sb + OFF_PH + swzT(rB, c16lo), qb[0], qb[1], qb[2], qb[3]);
                    }
                }
                if (k > 0) { pa *= ua; pb *= ub; ua *= CDEC; ub *= CDEC; }
            }
        }

        // --- prefetch chunk cc+1 into the other buffer ---
        if (cc < 15) {
            const u32 fb = sb + 16384 + (u32)((cc + 1) & 1) * 16384;
            const int col0 = 8 * (cc + 1);
#pragma unroll
            for (int t = 0; t < 4; t++) {
                int r = sr + t * 32;
                u32 sw = SWZ((u32)(r * 128 + sj * 16));
                CP_ASYNC16(fb + sw, fh_g + r * 128 + col0 + sj);
            }
        }
        CP_COMMIT();
        CP_WAIT1();       // chunk cc's feat tile landed
        __syncthreads();  // + phi stores visible

        // --- MMA: 4 k-steps, A-frags via ldmatrix.trans on the [m][ch] tile ---
#pragma unroll
        for (int ks = 0; ks < 4; ks++) {
            const u32 mb = (u32)(ks * 32);       // feat byte col base
            u32 ap[4][4], bh[4][2];
#pragma unroll
            for (int mt = 0; mt < 4; mt++) {
                u32 tRow = (u32)(ks * 16) + tRowL;
                u32 c16  = (u32)(wm * 8 + mt * 2) + tC16L;
                ldsm4t(ap[mt][0], ap[mt][1], ap[mt][2], ap[mt][3],
                       sb + OFF_PH + swzT(tRow, c16));
            }
#pragma unroll
            for (int nb = 0; nb < 4; nb++) {
                u32 row = (u32)(wn * 32 + nb * 8) + bRow;
                u32 off = SWZ(row * 128 + mb + bColB);
                ldsm2(bh[nb][0], bh[nb][1], fbase + off);
            }
#pragma unroll
            for (int mt = 0; mt < 4; mt++)
#pragma unroll
                for (int nb = 0; nb < 4; nb++)
                    mma16816h(c[mt][nb], ap[mt], bh[nb]);
        }
        __syncthreads();   // phi tile consumed; next chunk may overwrite
    }

    // --- store C: rows ch (i contiguous), coalesced float2 ---
    const size_t obase = ((size_t)(b * NPTS + n0)) * NB * DI;
#pragma unroll
    for (int mt = 0; mt < 4; mt++) {
        int ch0 = wm * 64 + mt * 16 + (lane >> 2);
        float* r0 = g_tmp + obase + (size_t)ch0 * DI;
#pragma unroll
        for (int nb = 0; nb < 4; nb++) {
            int i0 = wn * 32 + nb * 8 + (lane & 3) * 2;
            if (i0 < DI) {
                *(float2*)(r0 + i0)          = make_float2(c[mt][nb][0], c[mt][nb][1]);
                *(float2*)(r0 + 8 * DI + i0) = make_float2(c[mt][nb][2], c[mt][nb][3]);
            }
        }
    }
}

// ---------------- kernel B: y = W x tmp (FFMA2) + gating epilogue ----------------
#define TB 288

__global__ __launch_bounds__(TB, 2) void se3convB(
    const float* __restrict__ W,      // [NB, DO, DI]
    float* __restrict__ out)          // [B, SO, N]
{
    __shared__ __align__(16) float Ts[2][DI][20];    // [buf][i][n], pitch 20
    __shared__ __align__(16) float y_s[DO][16];
    const int tid = threadIdx.x;
    const int b  = blockIdx.x >> 6;
    const int n0 = (blockIdx.x & 63) * 16;
    const int op = tid >> 2;          // 0..71 -> o pair (op, op+72)
    const int nq = tid & 3;           // n base = nq*4
    const float* tbase = g_tmp + ((size_t)(b * NPTS + n0)) * NB * DI;

    // prologue: stage k = 0 (16 n x 26 float4)
    for (int idx = tid; idx < 416; idx += TB) {
        int n = idx / 26, q = idx - n * 26;
        float4 v = ((const float4*)(tbase + ((size_t)n * NB) * DI))[q];
        Ts[0][4 * q + 0][n] = v.x; Ts[0][4 * q + 1][n] = v.y;
        Ts[0][4 * q + 2][n] = v.z; Ts[0][4 * q + 3][n] = v.w;
    }
    __syncthreads();

    ull a0[2] = {0, 0}, a1[2] = {0, 0};

    for (int k = 0; k < NB; k++) {
        const int buf = k & 1;
        if (k + 1 < NB) {
            for (int idx = tid; idx < 416; idx += TB) {
                int n = idx / 26, q = idx - n * 26;
                float4 v = ((const float4*)(tbase + ((size_t)n * NB + (k + 1)) * DI))[q];
                Ts[buf ^ 1][4 * q + 0][n] = v.x; Ts[buf ^ 1][4 * q + 1][n] = v.y;
                Ts[buf ^ 1][4 * q + 2][n] = v.z; Ts[buf ^ 1][4 * q + 3][n] = v.w;
            }
        }
        const float4* w0 = (const float4*)(W + ((size_t)k * DO + op) * DI);
        const float4* w1 = (const float4*)(W + ((size_t)k * DO + op + 72) * DI);
#pragma unroll 2
        for (int q = 0; q < 26; q++) {
            float4 wa = w0[q];
            float4 wb = w1[q];
#pragma unroll
            for (int j = 0; j < 4; j++) {
                int i = 4 * q + j;
                F4U t;
                t.f = *(const float4*)&Ts[buf][i][nq * 4];
                float wav = (j == 0) ? wa.x : (j == 1) ? wa.y : (j == 2) ? wa.z : wa.w;
                float wbv = (j == 0) ? wb.x : (j == 1) ? wb.y : (j == 2) ? wb.z : wb.w;
                ull wap = pack2(wav, wav), wbp = pack2(wbv, wbv);
                a0[0] = fma2(t.u[0], wap, a0[0]);
                a0[1] = fma2(t.u[1], wap, a0[1]);
                a1[0] = fma2(t.u[0], wbp, a1[0]);
                a1[1] = fma2(t.u[1], wbp, a1[1]);
            }
        }
        __syncthreads();
    }

    // spill y to smem
    {
        float v0, v1;
#pragma unroll
        for (int q = 0; q < 2; q++) {
            unpack2(a0[q], v0, v1);
            y_s[op][nq * 4 + 2 * q]     = v0;
            y_s[op][nq * 4 + 2 * q + 1] = v1;
            unpack2(a1[q], v0, v1);
            y_s[op + 72][nq * 4 + 2 * q]     = v0;
            y_s[op + 72][nq * 4 + 2 * q + 1] = v1;
        }
    }
    __syncthreads();

    // gating epilogue (SO*16 = 1920 elements)
    for (int idx = tid; idx < SO * 16; idx += TB) {
        int cc = idx >> 4, n = idx & 15;
        float v = y_s[cc][n];
        float res;
        if (cc < 32) {
            res = fmaxf(v, 0.0f);
        } else if (cc < 80) {
            int j = (cc - 32) / 3;
            float g = y_s[120 + j][n];
            res = v * __fdividef(1.0f, 1.0f + __expf(-g));
        } else {
            int j = (cc - 80) / 5;
            float g = y_s[136 + j][n];
            res = v * __fdividef(1.0f, 1.0f + __expf(-g));
        }
        out[((size_t)b * SO + cc) * NPTS + n0 + n] = res;
    }
}

// ---------------- launcher ----------------
extern "C" void kernel_launch(void* const* d_in, const int* in_sizes, int n_in,
                              void* d_out, int out_size) {
    (void)in_sizes; (void)n_in; (void)out_size;
    const float* feat = (const float*)d_in[0];
    const float* diff = (const float*)d_in[1];
    const float* mask = (const float*)d_in[2];
    const float* W    = (const float*)d_in[3];

    cudaFuncSetAttribute(se3convA, cudaFuncAttributeMaxDynamicSharedMemorySize, SMEMA_BYTES);

    featSplit<<<(BATCH * 128 * MPTS) / 256, 256>>>(feat);
    se3convA<<<BATCH * (NPTS / 8), 256, SMEMA_BYTES>>>(diff, mask);
    se3convB<<<BATCH * (NPTS / 16), TB>>>(W, (float*)d_out);
}